// round 2
// baseline (speedup 1.0000x reference)
#include <cuda_runtime.h>

// LatentDT: z[n,v] = clamp(min over edges on root->v path of +-(x[n].A[s]), 0, 1)
// (path-min starts at 1, so values are always <= 1; clamp-low prunes subtrees)
// Expected surviving nodes per row ~ DEPTH+1 -> output-store-bound kernel.

#define DEPTH     10
#define NB_SPLIT  1023   // 2^10 - 1
#define NB_NODES  2047   // 2^11 - 1
#define KDIM      128

#define THREADS          256
#define WARPS_PER_BLOCK  8
#define ROWS_PER_BLOCK   8
// 8 rows * 2047 floats = 16376 floats = 4094 float4 exactly, and
// 8*2047*4 bytes = 65504 is a multiple of 16 -> every block region is
// float4-aligned (given 256B-aligned base) with no remainder.
#define F4_PER_BLOCK     ((ROWS_PER_BLOCK * NB_NODES) / 4)   // 4094

__global__ void __launch_bounds__(THREADS, 8) latentdt_kernel(
    const float* __restrict__ x,
    const float* __restrict__ A,
    float* __restrict__ out,
    int rows)
{
    const int tid  = threadIdx.x;
    const int lane = tid & 31;
    const int warp = tid >> 5;
    const int row0 = blockIdx.x * ROWS_PER_BLOCK;
    const int row  = row0 + warp;

    // ---- Block-cooperative zero fill: perfectly aligned float4 stream ----
    const float4 z4 = make_float4(0.f, 0.f, 0.f, 0.f);
    if (row0 + ROWS_PER_BLOCK <= rows) {
        float4* blk = reinterpret_cast<float4*>(out + (size_t)row0 * NB_NODES);
        #pragma unroll 4
        for (int i = tid; i < F4_PER_BLOCK; i += THREADS) blk[i] = z4;
    } else {
        // tail block: scalar fill (not hit for rows % 8 == 0)
        const size_t base  = (size_t)row0 * NB_NODES;
        const size_t total = (size_t)rows * NB_NODES;
        for (size_t i = base + tid; i < total; i += THREADS) out[i] = 0.0f;
    }
    __syncthreads();   // fill visible before per-warp scatter overwrites

    if (row >= rows) return;

    const float4* __restrict__ Af4 = reinterpret_cast<const float4*>(A);
    const float4  xv = __ldg(reinterpret_cast<const float4*>(
                                 x + (size_t)row * KDIM) + lane);
    float* outrow = out + (size_t)row * NB_NODES;
    if (lane == 0) outrow[0] = 1.0f;   // root: clamp(1) = 1

    // ---- Warp-uniform DFS with child prefetch ----
    int   st_node[DEPTH + 1];
    float st_q[DEPTH + 1];
    int   sp   = 0;
    int   node = 0;
    float q    = 1.0f;

    float4 av = __ldg(Af4 + lane);      // A row of current node (node 0)
    float4 av_top;                       // A row cached for current stack top
    bool   top_cached = false;

    while (true) {
        const int  cl         = 2 * node + 1;        // left child
        const bool childSplit = (cl < NB_SPLIT);     // both children split nodes

        // Prefetch both children's A rows BEFORE the dependent shuffle chain.
        float4 avL, avR;
        if (childSplit) {
            avL = __ldg(Af4 + (size_t)cl * 32 + lane);
            avR = __ldg(Af4 + (size_t)(cl + 1) * 32 + lane);
        }

        // dot(x_row, A[node]): per-lane float4 FMA + butterfly reduce
        float p = fmaf(xv.x, av.x,
                  fmaf(xv.y, av.y,
                  fmaf(xv.z, av.z, xv.w * av.w)));
        p += __shfl_xor_sync(0xffffffffu, p, 16);
        p += __shfl_xor_sync(0xffffffffu, p, 8);
        p += __shfl_xor_sync(0xffffffffu, p, 4);
        p += __shfl_xor_sync(0xffffffffu, p, 2);
        p += __shfl_xor_sync(0xffffffffu, p, 1);
        // p is warp-uniform now.

        const float qL = fminf(q, p);    // <= 1 always (q starts at 1)
        const float qR = fminf(q, -p);

        if (lane == 0) {
            if (qL > 0.0f) outrow[cl]     = qL;
            if (qR > 0.0f) outrow[cl + 1] = qR;
        }

        const bool goL = childSplit && (qL > 0.0f);
        const bool goR = childSplit && (qR > 0.0f);

        if (goL) {
            if (goR) {                   // push right child + cache its A row
                st_node[sp] = cl + 1; st_q[sp] = qR; ++sp;
                av_top = avR; top_cached = true;
            }
            node = cl;  q = qL;  av = avL;
        } else if (goR) {
            node = cl + 1;  q = qR;  av = avR;
        } else {
            if (sp == 0) break;
            --sp;
            node = st_node[sp];  q = st_q[sp];
            if (top_cached) {            // stack top always == last push
                av = av_top; top_cached = false;
            } else {
                av = __ldg(Af4 + (size_t)node * 32 + lane);
            }
        }
    }
}

extern "C" void kernel_launch(void* const* d_in, const int* in_sizes, int n_in,
                              void* d_out, int out_size)
{
    const float* x = (const float*)d_in[0];   // [rows, 128]
    const float* A = (const float*)d_in[1];   // [1023, 128]
    float* out = (float*)d_out;               // [rows, 2047]

    const int rows = out_size / NB_NODES;     // 32768

    const int blocks = (rows + ROWS_PER_BLOCK - 1) / ROWS_PER_BLOCK;
    latentdt_kernel<<<blocks, THREADS>>>(x, A, out, rows);
}

// round 4
// speedup vs baseline: 1.0333x; 1.0333x over previous
#include <cuda_runtime.h>

// LatentDT: z[n,v] = clamp(min over edges on root->v path of +-(x[n].A[s]), 0, 1)
// Path-min starts at 1 (so all outputs <= 1); once it goes <= 0 the whole
// subtree clamps to 0 -> pruned DFS visits ~DEPTH+1 nodes per row.
// Kernel is output-write-bandwidth bound (268 MB of stores).

#define DEPTH     10
#define NB_SPLIT  1023   // 2^10 - 1
#define NB_NODES  2047   // 2^11 - 1
#define KDIM      128

#define THREADS          256
#define ROWS_PER_BLOCK   8
// 8 rows * 2047 floats = 16376 floats = 4094 float4 exactly; block regions are
// 16B-aligned (65504 B per block, base 256B-aligned) with no remainder.
#define F4_PER_BLOCK     ((ROWS_PER_BLOCK * NB_NODES) / 4)   // 4094

__global__ void __launch_bounds__(THREADS, 8) latentdt_kernel(
    const float* __restrict__ x,
    const float* __restrict__ A,
    float* __restrict__ out,
    int rows)
{
    const int tid  = threadIdx.x;
    const int lane = tid & 31;
    const int warp = tid >> 5;
    const int row0 = blockIdx.x * ROWS_PER_BLOCK;
    const int row  = row0 + warp;

    // ---- Block-cooperative zero fill: aligned float4 streaming stores ----
    const float4 z4 = make_float4(0.f, 0.f, 0.f, 0.f);
    if (row0 + ROWS_PER_BLOCK <= rows) {
        float4* blk = reinterpret_cast<float4*>(out + (size_t)row0 * NB_NODES);
        for (int i = tid; i < F4_PER_BLOCK; i += THREADS) {
            __stcs(blk + i, z4);          // evict-first: don't thrash L2
        }
    } else {
        const size_t base  = (size_t)row0 * NB_NODES;
        const size_t total = (size_t)rows * NB_NODES;
        for (size_t i = base + tid; i < total; i += THREADS) out[i] = 0.0f;
    }
    __syncthreads();   // fill visible/ordered before per-warp scatter stores

    if (row >= rows) return;

    // Load this row of x: 128 floats, 4 per lane (512B, coalesced).
    const float4 xv = __ldg(reinterpret_cast<const float4*>(
                                x + (size_t)row * KDIM) + lane);

    float* outrow = out + (size_t)row * NB_NODES;
    if (lane == 0) __stcg(outrow + 0, 1.0f);   // root: clamp(1) = 1

    // ---- Warp-uniform lazy DFS (load A[node] only when node is visited) ----
    int   st_node[DEPTH + 1];
    float st_q[DEPTH + 1];
    int   sp   = 0;
    int   node = 0;
    float q    = 1.0f;

    while (true) {
        // dot(x_row, A[node]): per-lane float4 FMA + butterfly reduce
        const float4 av = __ldg(reinterpret_cast<const float4*>(
                                    A + (size_t)node * KDIM) + lane);
        float p = fmaf(xv.x, av.x,
                  fmaf(xv.y, av.y,
                  fmaf(xv.z, av.z, xv.w * av.w)));
        p += __shfl_xor_sync(0xffffffffu, p, 16);
        p += __shfl_xor_sync(0xffffffffu, p, 8);
        p += __shfl_xor_sync(0xffffffffu, p, 4);
        p += __shfl_xor_sync(0xffffffffu, p, 2);
        p += __shfl_xor_sync(0xffffffffu, p, 1);
        // p is warp-uniform now.

        const float qL = fminf(q, p);     // always <= 1 (q starts at 1)
        const float qR = fminf(q, -p);
        const int cl = 2 * node + 1;      // left child; cl+1 = right child

        if (lane == 0) {
            if (qL > 0.0f) __stcg(outrow + cl,     qL);
            if (qR > 0.0f) __stcg(outrow + cl + 1, qR);
        }

        // Recurse only into split-node children with positive path-min.
        const bool childIsSplit = (cl < NB_SPLIT);
        const bool goL = childIsSplit && (qL > 0.0f);
        const bool goR = childIsSplit && (qR > 0.0f);

        if (goL) {
            if (goR) { st_node[sp] = cl + 1; st_q[sp] = qR; ++sp; }
            node = cl;  q = qL;
        } else if (goR) {
            node = cl + 1;  q = qR;
        } else {
            if (sp == 0) break;
            --sp;
            node = st_node[sp];  q = st_q[sp];
        }
    }
}

extern "C" void kernel_launch(void* const* d_in, const int* in_sizes, int n_in,
                              void* d_out, int out_size)
{
    const float* x = (const float*)d_in[0];   // [rows, 128]
    const float* A = (const float*)d_in[1];   // [1023, 128]
    float* out = (float*)d_out;               // [rows, 2047]

    const int rows = out_size / NB_NODES;     // 32768

    const int blocks = (rows + ROWS_PER_BLOCK - 1) / ROWS_PER_BLOCK;
    latentdt_kernel<<<blocks, THREADS>>>(x, A, out, rows);
}

// round 5
// speedup vs baseline: 1.0678x; 1.0334x over previous
#include <cuda_runtime.h>
#include <cstdint>

// LatentDT: z[n,v] = clamp(min over edges on root->v path of +-(x[n].A[s]), 0, 1)
// Path-min starts at 1 (all outputs <= 1); once it goes <= 0 the whole subtree
// clamps to 0 -> pruned DFS visits ~DEPTH+1 nodes per row.
// Output-write-bandwidth bound (268 MB of stores).
//
// R5: exactly the 56us v1 structure (per-warp fill + __syncwarp + lazy DFS,
// default-policy stores), with ONLY the fill vectorized to float4.

#define DEPTH     10
#define NB_SPLIT  1023   // 2^10 - 1
#define NB_NODES  2047   // 2^11 - 1
#define KDIM      128

__global__ void __launch_bounds__(256, 8) latentdt_kernel(
    const float* __restrict__ x,
    const float* __restrict__ A,
    float* __restrict__ out,
    int rows)
{
    const int warp_global = (blockIdx.x * blockDim.x + threadIdx.x) >> 5;
    const int lane = threadIdx.x & 31;
    if (warp_global >= rows) return;

    // Load this row of x: 128 floats, 4 per lane (512B, coalesced, aligned).
    const float4 xv = __ldg(reinterpret_cast<const float4*>(
                                x + (size_t)warp_global * KDIM) + lane);

    float* outrow = out + (size_t)warp_global * NB_NODES;

    // ---- Per-warp vectorized zero fill of own row (default cache policy) ----
    // Row size 2047 floats (8188 B); base alignment mod 16 cycles {0,12,8,4},
    // so peel a <=3-float head to reach 16B alignment, then float4 body, then
    // a <=3-float tail.
    {
        const int headN = (int)(((16u - ((uint32_t)(uintptr_t)outrow & 15u)) & 15u) >> 2); // 0..3
        if (lane < headN) outrow[lane] = 0.0f;

        const int bodyN = (NB_NODES - headN) >> 2;               // float4 count
        float4* body = reinterpret_cast<float4*>(outrow + headN);
        const float4 z4 = make_float4(0.f, 0.f, 0.f, 0.f);
        #pragma unroll 4
        for (int i = lane; i < bodyN; i += 32) body[i] = z4;

        const int tail0 = headN + (bodyN << 2);
        if (lane < NB_NODES - tail0) outrow[tail0 + lane] = 0.0f;
    }
    __syncwarp();               // order fill stores before lane-0 scatter stores
    if (lane == 0) outrow[0] = 1.0f;   // root: clamp(1) = 1

    // ---- Warp-uniform lazy DFS (load A[node] only when visited) ----
    int   st_node[DEPTH + 1];
    float st_q[DEPTH + 1];
    int   sp   = 0;
    int   node = 0;
    float q    = 1.0f;

    while (true) {
        // dot(x_row, A[node]) : float4 per lane + butterfly reduce
        const float4 av = __ldg(reinterpret_cast<const float4*>(
                                    A + (size_t)node * KDIM) + lane);
        float p = fmaf(xv.x, av.x,
                  fmaf(xv.y, av.y,
                  fmaf(xv.z, av.z, xv.w * av.w)));
        p += __shfl_xor_sync(0xffffffffu, p, 16);
        p += __shfl_xor_sync(0xffffffffu, p, 8);
        p += __shfl_xor_sync(0xffffffffu, p, 4);
        p += __shfl_xor_sync(0xffffffffu, p, 2);
        p += __shfl_xor_sync(0xffffffffu, p, 1);
        // p is now warp-uniform.

        const float qL = fminf(q, p);     // always <= 1 (q starts at 1)
        const float qR = fminf(q, -p);
        const int cl = 2 * node + 1;      // left child; cl+1 = right child

        if (lane == 0) {
            if (qL > 0.0f) outrow[cl]     = qL;
            if (qR > 0.0f) outrow[cl + 1] = qR;
        }

        // Recurse only into split-node children with positive path-min.
        const bool childIsSplit = (cl < NB_SPLIT);
        const bool goL = childIsSplit && (qL > 0.0f);
        const bool goR = childIsSplit && (qR > 0.0f);

        if (goL) {
            if (goR) { st_node[sp] = cl + 1; st_q[sp] = qR; ++sp; }
            node = cl;  q = qL;
        } else if (goR) {
            node = cl + 1;  q = qR;
        } else {
            if (sp == 0) break;
            --sp;
            node = st_node[sp];  q = st_q[sp];
        }
    }
}

extern "C" void kernel_launch(void* const* d_in, const int* in_sizes, int n_in,
                              void* d_out, int out_size)
{
    const float* x = (const float*)d_in[0];   // [rows, 128]
    const float* A = (const float*)d_in[1];   // [1023, 128]
    float* out = (float*)d_out;               // [rows, 2047]

    const int rows = out_size / NB_NODES;     // 32768

    const int threads = 256;                  // 8 warps/block, 1 row/warp
    const int warps_per_block = threads / 32;
    const int blocks = (rows + warps_per_block - 1) / warps_per_block;

    latentdt_kernel<<<blocks, threads>>>(x, A, out, rows);
}